// round 16
// baseline (speedup 1.0000x reference)
#include <cuda_runtime.h>
#include <cuda_bf16.h>

#define NR 128
#define NS 16
#define NC 4
#define NT 4
#define TM 16      // m-tile per block
#define TMH 8      // m's per thread (sub-block)
#define NBLK ((NS*NR)/TM)   // 128 blocks
#define NM (NS*NR)          // 2048 k-space points

// Dynamic smem layout (float2 units):
//   sA   [NT][TM][NR]      : 8192 float2  (64 KB)
//   sB   [NT][NR][TM]      : 8192 float2  (64 KB)
//   sF   [NT][2][TM][24]   : 1536 float2  (12 KB)  factored sincos
//   sred [16][TMH]         :  128 float2  ( 1 KB)
#define SA_N   (NT*TM*NR)
#define SB_N   (NT*NR*TM)
#define SF_N   (NT*2*TM*24)
#define SRED_N (16*TMH)
#define DYNSMEM ((SA_N + SB_N + SF_N + SRED_N) * (int)sizeof(float2))

// Warped coil images, transposed: W[t][c][j][i] = csm[c,i,j] * x[si,sj]
__device__ float g_W[NT*NC*NR*NR];  // 1 MB

__global__ void prep_kernel(const float* __restrict__ x,
                            const float* __restrict__ csm,
                            const float* __restrict__ flow) {
    int i = blockIdx.x;      // image row
    int t = blockIdx.y;      // motion state
    int j = threadIdx.x;     // image col
    int base = ((i*NR + j)*2)*NT + t;        // flow[i,j,d,t]
    float fi = flow[base];
    float fj = flow[base + NT];
    int si = __float2int_rn((float)i + fi);  // round half-to-even == jnp.round
    int sj = __float2int_rn((float)j + fj);
    si = min(max(si, 0), NR-1);
    sj = min(max(sj, 0), NR-1);
    float xv = __ldg(&x[si*NR + sj]);
#pragma unroll
    for (int c = 0; c < NC; c++) {
        g_W[((t*NC + c)*NR + j)*NR + i] = csm[(c*NR + i)*NR + j] * xv;
    }
}

__device__ __forceinline__ unsigned long long pack2(float lo, float hi) {
    unsigned long long r;
    asm("mov.b64 %0, {%1, %2};" : "=l"(r) : "f"(lo), "f"(hi));
    return r;
}

// (accR,accI) += (bx,by) * (w,w) in ONE f32x2 FMA
__device__ __forceinline__ void fma2(float2& acc, float bx, float by,
                                     unsigned long long wd) {
    unsigned long long b = pack2(bx, by);
    unsigned long long a = *reinterpret_cast<unsigned long long*>(&acc);
    asm("fma.rn.f32x2 %0, %1, %2, %0;" : "+l"(a) : "l"(b), "l"(wd));
    acc = *reinterpret_cast<float2*>(&a);
}

// Separable NDFT: ks[m,c] = sum_i A[m,i] * ( sum_j B[m,j] * W[t][c][j][i] )
// R16: ALL four t's phase tables are built up front (141 KB dynamic smem),
// then the mainloop runs 4x128 j's with ZERO barriers — one long fma burst
// where the W register-prefetch pipeline never drains.
__global__ __launch_bounds__(512, 1)
void nufft_kernel(const float* __restrict__ traj, float* __restrict__ outf,
                  int out_mode) {
    extern __shared__ float2 dyn[];
    float2* sA   = dyn;                 // [t][mi][p]
    float2* sB   = sA + SA_N;           // [t][p][mi]
    float2* sF   = sB + SB_N;           // [t][d][mi][u]
    float2* sred = sF + SF_N;           // [warp][mi]

    int tid = threadIdx.x;   // 512
    int s  = tid >> 8;          // m-half: 0 or 1
    int c  = (tid >> 6) & 3;    // coil
    int ti = tid & 63;          // i-pair; i = 2ti, 2ti+1
    int m0 = blockIdx.x * TM;
    int mb = s * TMH;

    // ---- Phase 1a: factored sincos for ALL t (6 sincospif per thread) ----
    for (int v = tid; v < NT*2*TM*24; v += 512) {
        int t   = v / (2*TM*24);
        int rem = v - t*(2*TM*24);
        int d   = rem / (TM*24);
        int r2  = rem - d*(TM*24);
        int mi  = r2 / 24;
        int u   = r2 - mi*24;
        float k = traj[((m0 + mi)*NT + t)*2 + d];
        float arg = (u < 16) ? (-16.f * k * (float)(u - 8))   // Ca[a], a=u-8
                             : (-2.f  * k * (float)(u - 16)); // Cb[b], b=u-16
        float sn, cs; sincospif(arg, &sn, &cs);
        sF[((t*2 + d)*TM + mi)*24 + u] = make_float2(cs, sn);
    }
    __syncthreads();

    // ---- Phase 1b: expand into sA/sB for ALL t (one cmul per entry) ----
    for (int v = tid; v < NT*2*TM*NR; v += 512) {
        int t   = v >> 12;
        int rem = v & 4095;
        int d   = rem >> 11;
        int r2  = rem & 2047;
        int mi, p;
        if (d == 0) { mi = r2 >> 7; p = r2 & 127; }
        else        { p = r2 >> 4;  mi = r2 & 15; }  // mi-fastest: conflict-free STS
        int q = p - 64;
        int a = (q >> 3) + 8;   // 0..15
        int b = q & 7;          // 0..7
        float2 ca = sF[((t*2 + d)*TM + mi)*24 + a];
        float2 cb = sF[((t*2 + d)*TM + mi)*24 + 16 + b];
        float2 val = make_float2(ca.x*cb.x - ca.y*cb.y,
                                 ca.x*cb.y + ca.y*cb.x);
        if (d == 0) sA[(t*TM + mi)*NR + p] = val;
        else        sB[(t*NR + p)*TM + mi] = val;
    }
    __syncthreads();

    // ---- Phase 2: barrier-free mainloop over all 4 t ----
    float2 acc[TMH];
#pragma unroll
    for (int mi = 0; mi < TMH; mi++) acc[mi] = make_float2(0.f, 0.f);

    for (int t = 0; t < NT; t++) {
        const float* Wp = g_W + ((t*NC + c)*NR)*NR + 2*ti;
        const float2* sBt = sB + t*NR*TM + mb;
        float2 g0[TMH], g1[TMH];
#pragma unroll
        for (int mi = 0; mi < TMH; mi++) {
            g0[mi] = make_float2(0.f, 0.f);
            g1[mi] = make_float2(0.f, 0.f);
        }

        float2 wbuf[2][4];
#pragma unroll
        for (int p = 0; p < 4; p++)
            wbuf[0][p] = *reinterpret_cast<const float2*>(Wp + p*NR);

#pragma unroll 2
        for (int jb = 0; jb < NR; jb += 4) {
            int cur = (jb >> 2) & 1;
            // Prefetch next j-batch FIRST: load->use distance ~1 batch
            if (jb + 4 < NR) {
#pragma unroll
                for (int p = 0; p < 4; p++)
                    wbuf[cur ^ 1][p] =
                        *reinterpret_cast<const float2*>(Wp + (jb + 4 + p)*NR);
            }
#pragma unroll
            for (int p = 0; p < 4; p++) {
                float2 w2 = wbuf[cur][p];
                unsigned long long wd0 = pack2(w2.x, w2.x);
                unsigned long long wd1 = pack2(w2.y, w2.y);
                const float4* brow =
                    reinterpret_cast<const float4*>(sBt + (jb + p)*TM);
#pragma unroll
                for (int mh = 0; mh < TMH/2; mh++) {
                    float4 b2 = brow[mh];              // broadcast LDS.128
                    fma2(g0[2*mh  ], b2.x, b2.y, wd0); // i = 2ti
                    fma2(g0[2*mh+1], b2.z, b2.w, wd0);
                    fma2(g1[2*mh  ], b2.x, b2.y, wd1); // i = 2ti+1
                    fma2(g1[2*mh+1], b2.z, b2.w, wd1);
                }
            }
        }

        // Fold A[m,i] for both i rows, accumulate over t (registers only)
#pragma unroll
        for (int mi = 0; mi < TMH; mi++) {
            float4 a01 = reinterpret_cast<const float4*>(
                             sA + (t*TM + mb + mi)*NR)[ti];
            acc[mi].x += a01.x*g0[mi].x - a01.y*g0[mi].y
                       + a01.z*g1[mi].x - a01.w*g1[mi].y;
            acc[mi].y += a01.x*g0[mi].y + a01.y*g0[mi].x
                       + a01.z*g1[mi].y + a01.w*g1[mi].x;
        }
    }

    // ---- Phase 3: reduce over i ----
    int warp = tid >> 5;
#pragma unroll
    for (int mi = 0; mi < TMH; mi++) {
        float r = acc[mi].x, q = acc[mi].y;
#pragma unroll
        for (int off = 16; off > 0; off >>= 1) {
            r += __shfl_down_sync(0xffffffffu, r, off);
            q += __shfl_down_sync(0xffffffffu, q, off);
        }
        if ((tid & 31) == 0) sred[warp*TMH + mi] = make_float2(r, q);
    }
    __syncthreads();
    if (tid < 64) {                     // 16 m x 4 coils per block
        int ml = tid >> 2;              // m within block 0..15
        int oc = tid & 3;
        int ss = ml >> 3, mi = ml & 7;
        int w0 = ss*8 + oc*2;
        float2 p0 = sred[w0*TMH + mi];
        float2 p1 = sred[(w0 + 1)*TMH + mi];
        float re = p0.x + p1.x;
        float im = p0.y + p1.y;
        int m = m0 + ml;
        int spoke = m >> 7;             // m = spoke*NR + read
        int read  = m & 127;
        int idx = (read*NS + spoke)*NC + oc;   // [read, spoke, coil]
        if (out_mode == 1) {            // planar (proven correct in R10)
            outf[idx]         = re;
            outf[NM*NC + idx] = im;
        } else if (out_mode == 2) {     // real only
            outf[idx] = re;
        } else {                        // interleaved complex64
            reinterpret_cast<float2*>(outf)[idx] = make_float2(re, im);
        }
    }
}

extern "C" void kernel_launch(void* const* d_in, const int* in_sizes, int n_in,
                              void* d_out, int out_size) {
    // Inputs proven f32, insertion order; size-based mapping kept for safety:
    //   x:16384  traj:16384  csm:65536  dcf:8192(unused)  flow:131072
    const float *x = nullptr, *traj = nullptr, *csm = nullptr, *flow = nullptr;
    for (int k = 0; k < n_in; k++) {
        int szk = in_sizes[k];
        if (szk == NC*NR*NR)          csm  = (const float*)d_in[k];
        else if (szk == NR*NR*2*NT)   flow = (const float*)d_in[k];
        else if (szk == NS*NR*NT)     { /* dcf unused */ }
        else if (szk == NR*NR) {
            if (!x) x = (const float*)d_in[k]; else traj = (const float*)d_in[k];
        }
    }
    if (!x || !traj || !csm || !flow) {
        x    = (const float*)d_in[0];
        traj = (const float*)d_in[1];
        csm  = (const float*)d_in[2];
        flow = (const float*)d_in[4];
    }

    int out_mode = 0;
    if (out_size == 2*NM*NC)      out_mode = 1;   // 16384 f32: planar re/im
    else if (out_size == NM*NC)   out_mode = 2;   // 8192: real only

    // Opt-in to >48KB dynamic smem (attribute set; not a stream op, capture-safe)
    cudaFuncSetAttribute(nufft_kernel,
                         cudaFuncAttributeMaxDynamicSharedMemorySize, DYNSMEM);

    prep_kernel<<<dim3(NR, NT), NR>>>(x, csm, flow);
    nufft_kernel<<<NBLK, 512, DYNSMEM>>>(traj, (float*)d_out, out_mode);
}